// round 6
// baseline (speedup 1.0000x reference)
#include <cuda_runtime.h>

// LSTM_53815940218945: single-layer LSTM, batch_first, then linear head.
// B=8192 (from out_size), T=256, I=1, H=50, O=1. fp32 throughout.
//
// Parallelization: 4 lanes per batch element (one per gate type i/f/g/o),
// 64 batch elements per 256-thread block -> B/64 = 128 blocks.
// Each block runs its batch slice through all T steps independently
// (no cross-block dependency).
//
// R4 fix: all shared arrays accessed via float4 are __align__(16).
// Plain `__shared__ float[]` is only 4B-aligned; ld/st.shared.v4 on a
// non-16B-aligned base -> "misaligned address" trap (R3 failure).

#define T_LEN   256
#define HID     50
#define HP      52      // H padded to multiple of 4 (float4 smem rows)
#define NG      4       // gates
#define EPB     64      // batch elements per block
#define NTHR    256     // threads per block (EPB * NG)
#define XCHUNK  16      // x timesteps staged in smem per refill

__device__ __forceinline__ float fast_ex2(float x) {
    float y; asm("ex2.approx.f32 %0, %1;" : "=f"(y) : "f"(x)); return y;
}
__device__ __forceinline__ float fast_rcp(float x) {
    float y; asm("rcp.approx.f32 %0, %1;" : "=f"(y) : "f"(x)); return y;
}

__global__ __launch_bounds__(NTHR, 1)
void lstm_fused_kernel(const float* __restrict__ x,
                       const float* __restrict__ W_ih,
                       const float* __restrict__ W_hh,
                       const float* __restrict__ b_ih,
                       const float* __restrict__ b_hh,
                       const float* __restrict__ W_lin,
                       const float* __restrict__ b_lin,
                       float* __restrict__ out)
{
    // ---- shared memory (static, < 48KB total), 16B-aligned for v4 access ----
    __shared__ __align__(16) float sW[NG * HID * HP]; // 41600B, padded rows
    __shared__ __align__(16) float sX[EPB * XCHUNK];  // 4KB staging of x
    __shared__ __align__(16) float sBias[NG * HID];   // b_ih + b_hh
    __shared__ __align__(16) float sWih[NG * HID];    // W_ih[:,0]
    __shared__ __align__(16) float sWl[HID];
    __shared__ float sblin;

    const int tid = threadIdx.x;

    // cooperative weight staging
    for (int i = tid; i < NG * HID * HP; i += NTHR) {
        int row = i / HP, k = i - row * HP;
        sW[i] = (k < HID) ? W_hh[row * HID + k] : 0.0f;
    }
    for (int i = tid; i < NG * HID; i += NTHR) {
        sBias[i] = b_ih[i] + b_hh[i];
        sWih[i]  = W_ih[i];                // I=1 -> W_ih is [4H,1]
    }
    if (tid < HID) sWl[tid] = W_lin[tid];  // W_lin is [1,H]
    if (tid == 0)  sblin = b_lin[0];

    const int q = tid & 3;        // gate type: 0=i 1=f 2=g 3=o
    const int e = tid >> 2;       // local batch element 0..63
    const long long bglob = (long long)blockIdx.x * EPB + e;
    const float* xbase = x + (long long)blockIdx.x * EPB * T_LEN;

    // recurrent state, replicated across the 4 lanes of a group
    float h[HP];
    float c[HID];
#pragma unroll
    for (int k = 0; k < HP; k++) h[k] = 0.0f;
#pragma unroll
    for (int j = 0; j < HID; j++) c[j] = 0.0f;

    // per-lane activation constants:
    //  sigmoid(z) = rcp(1 + ex2(-L2E*z))            -> act = 1*r + 0
    //  tanh(z)    = 2*rcp(1 + ex2(-2*L2E*z)) - 1    -> act = 2*r - 1
    const float L2E = 1.4426950408889634f;
    const float k1 = (q == 2) ? (-2.0f * L2E) : (-L2E);
    const float am = (q == 2) ? 2.0f : 1.0f;
    const float aa = (q == 2) ? -1.0f : 0.0f;

    float act[HID];   // dynamic-indexed in phase 1 -> local memory (L1-resident)

    const float* Wlane  = sW    + (q * HID) * HP;
    const float* Blane  = sBias + (q * HID);
    const float* WIlane = sWih  + (q * HID);

    for (int t = 0; t < T_LEN; t++) {
        // refill x staging every XCHUNK steps (whole block, uniform)
        if ((t & (XCHUNK - 1)) == 0) {
            __syncthreads();
            const int ee = tid >> 2;
            const int t4 = (tid & 3) * 4;
            const float4 v = *reinterpret_cast<const float4*>(
                xbase + ee * T_LEN + t + t4);
            *reinterpret_cast<float4*>(&sX[ee * XCHUNK + t4]) = v;
            __syncthreads();
        }
        const float xt = sX[e * XCHUNK + (t & (XCHUNK - 1))];

        // ---- phase 1: this lane's 50 gate preactivations + activation ----
#pragma unroll 2
        for (int j = 0; j < HID; j++) {
            const float* Wr = Wlane + j * HP;
            float a0 = 0.0f, a1 = 0.0f, a2 = 0.0f, a3 = 0.0f;
#pragma unroll
            for (int k4 = 0; k4 < HP / 4; k4++) {
                const float4 w = *reinterpret_cast<const float4*>(Wr + 4 * k4);
                a0 = fmaf(w.x, h[4 * k4 + 0], a0);
                a1 = fmaf(w.y, h[4 * k4 + 1], a1);
                a2 = fmaf(w.z, h[4 * k4 + 2], a2);
                a3 = fmaf(w.w, h[4 * k4 + 3], a3);
            }
            const float pre = fmaf(xt, WIlane[j], Blane[j]) + ((a0 + a1) + (a2 + a3));
            const float ee2 = fast_ex2(k1 * pre);
            const float r   = fast_rcp(1.0f + ee2);
            act[j] = fmaf(am, r, aa);
        }

        // ---- phase 2: exchange gates within the 4-lane group, update c,h ----
#pragma unroll
        for (int j = 0; j < HID; j++) {
            const float aj = act[j];
            const float gi = __shfl_sync(0xffffffffu, aj, 0, 4);
            const float gf = __shfl_sync(0xffffffffu, aj, 1, 4);
            const float gg = __shfl_sync(0xffffffffu, aj, 2, 4);
            const float go = __shfl_sync(0xffffffffu, aj, 3, 4);
            const float cj = fmaf(gf, c[j], gi * gg);
            c[j] = cj;
            const float ee2 = fast_ex2(-2.0f * L2E * cj);
            const float r   = fast_rcp(1.0f + ee2);
            h[j] = go * fmaf(2.0f, r, -1.0f);
        }
    }

    // ---- head: y = h_T @ W_lin^T + b_lin, one lane per group writes ----
    if (q == 0) {
        float y = sblin;
#pragma unroll
        for (int j = 0; j < HID; j++) y = fmaf(h[j], sWl[j], y);
        out[bglob] = y;
    }
}

extern "C" void kernel_launch(void* const* d_in, const int* in_sizes, int n_in,
                              void* d_out, int out_size) {
    const float* x     = (const float*)d_in[0];
    const float* W_ih  = (const float*)d_in[1];
    const float* W_hh  = (const float*)d_in[2];
    const float* b_ih  = (const float*)d_in[3];
    const float* b_hh  = (const float*)d_in[4];
    const float* W_lin = (const float*)d_in[5];
    const float* b_lin = (const float*)d_in[6];
    float* out = (float*)d_out;

    const int B = out_size;            // output is [B, 1]
    const int blocks = B / EPB;        // 8192/64 = 128
    lstm_fused_kernel<<<blocks, NTHR>>>(x, W_ih, W_hh, b_ih, b_hh,
                                        W_lin, b_lin, out);
}

// round 10
// speedup vs baseline: 2.0630x; 2.0630x over previous
#include <cuda_runtime.h>

// LSTM_53815940218945: B=8192, T=256, I=1, H=50, O=1, fp32.
//
// R6 redesign: register-tiled recurrent matvec.
//   - h lives in SMEM [EPB][HP], W_hh in SMEM [200][HP].
//   - Thread tile: ME=4 batch elements x (4 gates x NU=2 hidden units).
//     Each W/h fragment loaded once feeds a 4x8 FMA tile -> 4x less LDS
//     per FLOP than R4 (which was smem-crossbar bound at L1=80%).
//   - Packed fp32 math: fma.rn.f32x2 (FFMA2) along the k dimension; W and h
//     k-pairs are naturally contiguous, accumulators hold (even-k, odd-k)
//     partials folded once at the end.
//   - Each thread owns all 4 gates of its (e,u) pairs -> c/h update is fully
//     local (no shuffles).
// Block: EPB=32 elements, 200 threads (8 e-threads x 25 u-threads), 256 blocks.

#define T_LEN  256
#define HID    50
#define HP     52          // padded row stride (float4-aligned)
#define EPB    32          // batch elements per block
#define ME     4           // elements per thread
#define NU     2           // hidden units per thread (x4 gates = 8 W rows)
#define ET     (EPB/ME)    // 8 e-threads
#define UT     (HID/NU)    // 25 u-threads
#define NTHR   (ET*UT)     // 200 threads
#define NROW   (4*NU)      // 8 gate rows per thread

__device__ __forceinline__ float fast_ex2(float x) {
    float y; asm("ex2.approx.f32 %0, %1;" : "=f"(y) : "f"(x)); return y;
}
__device__ __forceinline__ float fast_rcp(float x) {
    float y; asm("rcp.approx.f32 %0, %1;" : "=f"(y) : "f"(x)); return y;
}
// packed fp32 FMA: d = a*b + d (two independent fp32 lanes)
__device__ __forceinline__ void ffma2(unsigned long long& d,
                                      unsigned long long a,
                                      unsigned long long b) {
    asm("fma.rn.f32x2 %0, %1, %2, %0;" : "+l"(d) : "l"(a), "l"(b));
}

union U64F2 { unsigned long long u; float2 f; };

__global__ __launch_bounds__(NTHR, 2)
void lstm_tiled_kernel(const float* __restrict__ x,
                       const float* __restrict__ W_ih,
                       const float* __restrict__ W_hh,
                       const float* __restrict__ b_ih,
                       const float* __restrict__ b_hh,
                       const float* __restrict__ W_lin,
                       const float* __restrict__ b_lin,
                       float* __restrict__ out)
{
    // 41600 + 6656 + 208 + 4 = 48468 B static smem (< 48KB limit)
    __shared__ __align__(16) float sW[4 * HID * HP];  // W_hh rows, zero-padded
    __shared__ __align__(16) float sH[EPB * HP];      // h_t
    __shared__ __align__(16) float sWl[HP];           // head weights
    __shared__ float sblin;

    const int tid = threadIdx.x;

    // ---- cooperative staging ----
    for (int i = tid; i < 4 * HID * HP; i += NTHR) {
        int row = i / HP, k = i - row * HP;
        sW[i] = (k < HID) ? W_hh[row * HID + k] : 0.0f;
    }
    for (int i = tid; i < EPB * HP; i += NTHR) sH[i] = 0.0f;
    if (tid < HP) sWl[tid] = (tid < HID) ? W_lin[tid] : 0.0f;
    if (tid == 0) sblin = b_lin[0];

    const int eIdx = tid % ET;   // 0..7
    const int uIdx = tid / ET;   // 0..24
    const int u0   = uIdx * NU;  // first hidden unit owned

    // per-thread invariants: 8 gate rows (q*HID + u0 + s)
    const float* Wrow[NROW];
    float biasR[NROW], wihR[NROW];
#pragma unroll
    for (int r = 0; r < NROW; r++) {
        const int q = r >> 1, s = r & 1;
        const int row = q * HID + u0 + s;
        Wrow[r]  = sW + row * HP;
        biasR[r] = b_ih[row] + b_hh[row];
        wihR[r]  = W_ih[row];            // I=1 -> W_ih is [4H,1]
    }

    // x base pointers for my 4 elements (em = m*ET + eIdx)
    const float* xp[ME];
#pragma unroll
    for (int m = 0; m < ME; m++)
        xp[m] = x + ((size_t)blockIdx.x * EPB + m * ET + eIdx) * T_LEN;

    float c[ME][NU];
#pragma unroll
    for (int m = 0; m < ME; m++)
#pragma unroll
        for (int s = 0; s < NU; s++) c[m][s] = 0.0f;

    const float L2E = 1.4426950408889634f;

    for (int t = 0; t < T_LEN; t++) {
        __syncthreads();   // h_t writes (prev iter) visible

        float xv[ME];
#pragma unroll
        for (int m = 0; m < ME; m++) xv[m] = __ldg(xp[m] + t);

        // ---- 8x4 register-tiled dot products over k (packed f32x2) ----
        unsigned long long acc[NROW][ME];
#pragma unroll
        for (int r = 0; r < NROW; r++)
#pragma unroll
            for (int m = 0; m < ME; m++) acc[r][m] = 0ull;

#pragma unroll
        for (int k4 = 0; k4 < HP / 4; k4++) {
            ulonglong2 wv[NROW];
#pragma unroll
            for (int r = 0; r < NROW; r++)
                wv[r] = *reinterpret_cast<const ulonglong2*>(Wrow[r] + 4 * k4);
#pragma unroll
            for (int m = 0; m < ME; m++) {
                const ulonglong2 hv = *reinterpret_cast<const ulonglong2*>(
                    &sH[(m * ET + eIdx) * HP + 4 * k4]);
#pragma unroll
                for (int r = 0; r < NROW; r++) {
                    ffma2(acc[r][m], wv[r].x, hv.x);
                    ffma2(acc[r][m], wv[r].y, hv.y);
                }
            }
        }

        __syncthreads();   // all sH reads complete before overwrite

        // ---- fold, activate, update c/h, write h_{t+1} ----
        float act[NROW][ME];
#pragma unroll
        for (int r = 0; r < NROW; r++) {
            const int q = r >> 1;
            const float k1 = (q == 2) ? (-2.0f * L2E) : (-L2E);
            const float am = (q == 2) ? 2.0f : 1.0f;
            const float aa = (q == 2) ? -1.0f : 0.0f;
#pragma unroll
            for (int m = 0; m < ME; m++) {
                U64F2 u; u.u = acc[r][m];
                const float pre = (u.f.x + u.f.y) + fmaf(xv[m], wihR[r], biasR[r]);
                const float e2 = fast_ex2(k1 * pre);
                const float rr = fast_rcp(1.0f + e2);
                act[r][m] = fmaf(am, rr, aa);
            }
        }
#pragma unroll
        for (int m = 0; m < ME; m++) {
            float2 hnew;
#pragma unroll
            for (int s = 0; s < NU; s++) {
                const float gi = act[0 * NU + s][m];
                const float gf = act[1 * NU + s][m];
                const float gg = act[2 * NU + s][m];
                const float go = act[3 * NU + s][m];
                const float cj = fmaf(gf, c[m][s], gi * gg);
                c[m][s] = cj;
                const float e2 = fast_ex2(-2.0f * L2E * cj);
                const float rr = fast_rcp(1.0f + e2);
                const float hj = go * fmaf(2.0f, rr, -1.0f);
                (s == 0 ? hnew.x : hnew.y) = hj;
            }
            // contiguous (u0, u0+1) pair, 8B aligned
            *reinterpret_cast<float2*>(&sH[(m * ET + eIdx) * HP + u0]) = hnew;
        }
    }

    __syncthreads();   // final h_T visible

    // ---- head: one thread per batch element ----
    if (tid < EPB) {
        const float* hrow = &sH[tid * HP];
        float y = sblin;
#pragma unroll
        for (int j = 0; j < HID; j++) y = fmaf(hrow[j], sWl[j], y);
        out[(size_t)blockIdx.x * EPB + tid] = y;
    }
}

extern "C" void kernel_launch(void* const* d_in, const int* in_sizes, int n_in,
                              void* d_out, int out_size) {
    const float* x     = (const float*)d_in[0];
    const float* W_ih  = (const float*)d_in[1];
    const float* W_hh  = (const float*)d_in[2];
    const float* b_ih  = (const float*)d_in[3];
    const float* b_hh  = (const float*)d_in[4];
    const float* W_lin = (const float*)d_in[5];
    const float* b_lin = (const float*)d_in[6];
    float* out = (float*)d_out;

    const int B = out_size;          // [B,1] output
    const int blocks = B / EPB;      // 8192/32 = 256
    lstm_tiled_kernel<<<blocks, NTHR>>>(x, W_ih, W_hh, b_ih, b_hh,
                                        W_lin, b_lin, out);
}

// round 11
// speedup vs baseline: 2.5445x; 1.2334x over previous
#include <cuda_runtime.h>

// LSTM_53815940218945: B=8192, T=256, I=1, H=50, O=1, fp32.
//
// R10: one CTA per SM, W_hh staged to smem ONCE per SM, two independent
// batch subgroups (28 elements each) inside the CTA synchronized with
// named barriers so their FFMA / MUFU / update phases interleave.
// sH is double-buffered -> exactly one barrier per timestep per subgroup.
// Grid 147 x 56 elements = balanced ~56 el/SM (R6: 64 on critical SMs
// + 2 barriers/step + convoy stalls -> fma pipe stuck at 49%).
//
// Math per thread: ME=4 elements x (4 gates x NU=2 units) register tile,
// packed fma.rn.f32x2 along k. Gate order (i,f,g,o).

#define T_LEN  256
#define HID    50
#define HP     52              // padded W row stride (float4 aligned)
#define ETX    7               // e-threads per subgroup
#define ME     4               // elements per thread
#define EPS    (ETX*ME)        // 28 elements per subgroup
#define UT     25              // u-threads (2 hidden units each)
#define NU     2
#define NROW   (4*NU)          // 8 gate rows per thread
#define ACT    (ETX*UT)        // 175 active threads per subgroup
#define SUBT   192             // padded (6 warps) per subgroup
#define SUBS   2
#define NTHR   (SUBS*SUBT)     // 384
#define EPB    (SUBS*EPS)      // 56 elements per block

// dynamic smem layout (bytes)
#define SM_W   0                       // 4*HID*HP*4 = 41600
#define SM_H   41600                   // + sub*11648 + buf*5824  (2 bufs/sub)
#define SUB_HB 11648                   // 2 * 28*52*4
#define BUF_HB 5824                    // 28*52*4
#define SM_WL  (SM_H + SUBS*SUB_HB)    // 64896, HP floats
#define SM_BL  (SM_WL + HP*4)          // 65104
#define SM_TOT 65152

__device__ __forceinline__ float fast_ex2(float x) {
    float y; asm("ex2.approx.f32 %0, %1;" : "=f"(y) : "f"(x)); return y;
}
__device__ __forceinline__ float fast_rcp(float x) {
    float y; asm("rcp.approx.f32 %0, %1;" : "=f"(y) : "f"(x)); return y;
}
__device__ __forceinline__ void ffma2(unsigned long long& d,
                                      unsigned long long a,
                                      unsigned long long b) {
    asm("fma.rn.f32x2 %0, %1, %2, %0;" : "+l"(d) : "l"(a), "l"(b));
}
union U64F2 { unsigned long long u; float2 f; };

__global__ __launch_bounds__(NTHR, 1)
void lstm_r10_kernel(const float* __restrict__ x,
                     const float* __restrict__ W_ih,
                     const float* __restrict__ W_hh,
                     const float* __restrict__ b_ih,
                     const float* __restrict__ b_hh,
                     const float* __restrict__ W_lin,
                     const float* __restrict__ b_lin,
                     float* __restrict__ out, int B)
{
    extern __shared__ __align__(16) char smem_raw[];
    float* sW  = reinterpret_cast<float*>(smem_raw + SM_W);
    float* sWl = reinterpret_cast<float*>(smem_raw + SM_WL);
    float* sBl = reinterpret_cast<float*>(smem_raw + SM_BL);

    const int tid = threadIdx.x;
    const int sub = tid / SUBT;          // subgroup 0/1
    const int st  = tid % SUBT;          // thread within subgroup
    const bool active = (st < ACT);

    float* sH = reinterpret_cast<float*>(smem_raw + SM_H + sub * SUB_HB);

    // ---- cooperative staging (whole block) ----
    for (int i = tid; i < 4 * HID * HP; i += NTHR) {
        int row = i / HP, k = i - row * HP;
        sW[i] = (k < HID) ? W_hh[row * HID + k] : 0.0f;
    }
    { // zero both h buffers of both subgroups
        float* hz = reinterpret_cast<float*>(smem_raw + SM_H);
        for (int i = tid; i < SUBS * SUB_HB / 4; i += NTHR) hz[i] = 0.0f;
    }
    if (tid < HP) sWl[tid] = (tid < HID) ? W_lin[tid] : 0.0f;
    if (tid == 0) sBl[0] = b_lin[0];
    __syncthreads();

    // clone inactive pad threads onto (e=0,u=0): identical computation,
    // h-store suppressed, so they stay barrier-convergent for bar.sync.
    const int eIdx = active ? (st % ETX) : 0;
    const int uIdx = active ? (st / ETX) : 0;
    const int u0   = uIdx * NU;

    const float* Wrow[NROW];
    float biasR[NROW], wihR[NROW];
#pragma unroll
    for (int r = 0; r < NROW; r++) {
        const int q = r >> 1, s = r & 1;
        const int row = q * HID + u0 + s;
        Wrow[r]  = sW + row * HP;
        biasR[r] = b_ih[row] + b_hh[row];
        wihR[r]  = W_ih[row];            // I=1
    }

    // my 4 batch elements; clamp out-of-range to element 0 (reads stay
    // in-bounds, stores are guarded).
    const size_t base = (size_t)blockIdx.x * EPB + sub * EPS;
    const float* xp[ME];
    bool valid[ME];
#pragma unroll
    for (int m = 0; m < ME; m++) {
        size_t ge = base + m * ETX + eIdx;
        valid[m] = (ge < (size_t)B);
        if (!valid[m]) ge = 0;
        xp[m] = x + ge * T_LEN;
    }

    float c[ME][NU];
#pragma unroll
    for (int m = 0; m < ME; m++)
#pragma unroll
        for (int s = 0; s < NU; s++) c[m][s] = 0.0f;

    const float L2E = 1.4426950408889634f;
    const int barid = sub + 1;

    for (int t = 0; t < T_LEN; t++) {
        const float* hin  = sH + (t & 1) * (BUF_HB / 4);
        float*       hout = sH + ((t + 1) & 1) * (BUF_HB / 4);

        float xv[ME];
#pragma unroll
        for (int m = 0; m < ME; m++) xv[m] = __ldg(xp[m] + t);

        // ---- 8x4 register-tiled matvec over k (packed f32x2) ----
        unsigned long long acc[NROW][ME];
#pragma unroll
        for (int r = 0; r < NROW; r++)
#pragma unroll
            for (int m = 0; m < ME; m++) acc[r][m] = 0ull;

#pragma unroll
        for (int k4 = 0; k4 < HP / 4; k4++) {
            ulonglong2 wv[NROW];
#pragma unroll
            for (int r = 0; r < NROW; r++)
                wv[r] = *reinterpret_cast<const ulonglong2*>(Wrow[r] + 4 * k4);
#pragma unroll
            for (int m = 0; m < ME; m++) {
                const ulonglong2 hv = *reinterpret_cast<const ulonglong2*>(
                    hin + (m * ETX + eIdx) * HP + 4 * k4);
#pragma unroll
                for (int r = 0; r < NROW; r++) {
                    ffma2(acc[r][m], wv[r].x, hv.x);
                    ffma2(acc[r][m], wv[r].y, hv.y);
                }
            }
        }

        // ---- fold + activations + cell update, all thread-local ----
        float act[NROW][ME];
#pragma unroll
        for (int r = 0; r < NROW; r++) {
            const int q = r >> 1;
            const float k1 = (q == 2) ? (-2.0f * L2E) : (-L2E);
            const float am = (q == 2) ? 2.0f : 1.0f;
            const float aa = (q == 2) ? -1.0f : 0.0f;
#pragma unroll
            for (int m = 0; m < ME; m++) {
                U64F2 u; u.u = acc[r][m];
                const float pre = (u.f.x + u.f.y) + fmaf(xv[m], wihR[r], biasR[r]);
                const float e2 = fast_ex2(k1 * pre);
                const float rr = fast_rcp(1.0f + e2);
                act[r][m] = fmaf(am, rr, aa);
            }
        }
#pragma unroll
        for (int m = 0; m < ME; m++) {
            float2 hnew;
#pragma unroll
            for (int s = 0; s < NU; s++) {
                const float gi = act[0 * NU + s][m];
                const float gf = act[1 * NU + s][m];
                const float gg = act[2 * NU + s][m];
                const float go = act[3 * NU + s][m];
                const float cj = fmaf(gf, c[m][s], gi * gg);
                c[m][s] = cj;
                const float e2 = fast_ex2(-2.0f * L2E * cj);
                const float rr = fast_rcp(1.0f + e2);
                const float hj = go * fmaf(2.0f, rr, -1.0f);
                (s == 0 ? hnew.x : hnew.y) = hj;
            }
            if (active)
                *reinterpret_cast<float2*>(hout + (m * ETX + eIdx) * HP + u0) = hnew;
        }

        // one named barrier per step, subgroup-scoped (6 warps)
        asm volatile("bar.sync %0, %1;" :: "r"(barid), "r"(SUBT) : "memory");
    }

    // ---- head: h_T lives in buffer 0 (T even). One thread per element. ----
    if (st < EPS) {
        const size_t ge = base + st;
        if (ge < (size_t)B) {
            const float* hrow = sH + st * HP;   // buf 0
            float y = sBl[0];
#pragma unroll
            for (int j = 0; j < HID; j++) y = fmaf(hrow[j], sWl[j], y);
            out[ge] = y;
        }
    }
}

extern "C" void kernel_launch(void* const* d_in, const int* in_sizes, int n_in,
                              void* d_out, int out_size) {
    const float* x     = (const float*)d_in[0];
    const float* W_ih  = (const float*)d_in[1];
    const float* W_hh  = (const float*)d_in[2];
    const float* b_ih  = (const float*)d_in[3];
    const float* b_hh  = (const float*)d_in[4];
    const float* W_lin = (const float*)d_in[5];
    const float* b_lin = (const float*)d_in[6];
    float* out = (float*)d_out;

    const int B = out_size;                    // [B,1]
    const int blocks = (B + EPB - 1) / EPB;    // 147 for B=8192

    static int smem_set = 0;                   // idempotent attribute set
    if (!smem_set) {
        cudaFuncSetAttribute(lstm_r10_kernel,
                             cudaFuncAttributeMaxDynamicSharedMemorySize,
                             SM_TOT);
        smem_set = 1;
    }
    lstm_r10_kernel<<<blocks, NTHR, SM_TOT>>>(x, W_ih, W_hh, b_ih, b_hh,
                                              W_lin, b_lin, out, B);
}